// round 10
// baseline (speedup 1.0000x reference)
#include <cuda_runtime.h>
#include <stdint.h>

// RadialTokenizer — fused quantize-to-smem + in-smem ring gather.
// Per (b,c) image: bin = floor((x*0.5+0.5)*255)-127 in [0,127].
// Phase A: stream image coalesced (float4), write bin bytes to 64KB smem.
// Phase B: warp w gathers rings (w, 15-w) from smem bins via offset lists,
// builds per-lane byte histograms (bank==lane, conflict-free, no atomics),
// then mean/std/median from the histogram. One barrier per block.
// Offset lists rebuilt each launch by 2 tiny kernels (atomic cursor; order
// within a ring is irrelevant for histograms).

#define HH 256
#define WW 256
#define NR 16
#define RSTRIDE 8192   // max ring population ~6233 < 8192

__device__ int g_cnt[NR];                                   // ring counts
__device__ __align__(128) uint16_t g_off[NR * RSTRIDE];     // ring px lists

// ring i <=> 64*i^2 < d2 <= 64*(i+1)^2 ; center pixel excluded.
__device__ __forceinline__ int ring_of(int x, int y) {
    int dx = x - 128, dy = y - 128;
    int d2 = dx * dx + dy * dy;
    if (d2 == 0 || d2 > 16384) return -1;
    int i = (int)(__fmul_rn(sqrtf((float)d2), 0.125f) + 0.999f) - 1;
    if (i < 0) i = 0;
    while (i > 0 && 64 * i * i >= d2) i--;
    while (d2 > 64 * (i + 1) * (i + 1)) i++;
    return i;
}

__global__ void k_zero() {
    if (threadIdx.x < NR) g_cnt[threadIdx.x] = 0;
}

__global__ void k_build() {
    int px = blockIdx.x * 256 + threadIdx.x;
    int x = px & 255, y = px >> 8;
    int r = ring_of(x, y);
    if (r >= 0) {
        int pos = atomicAdd(&g_cnt[r], 1);
        g_off[r * RSTRIDE + pos] = (uint16_t)px;
    }
}

// ---------------- main kernel ----------------
// Grid 768 (block = one (b,c)), 256 threads, 96KB dyn smem -> 2 blocks/SM.
// smem: bins u8[65536] (quantized image) + hist u8[8][4096] (per-warp).
// Hist byte addr = ((bin<<5)&0xF80) | (lane<<2) | (bin&3)  -> bank == lane.

__global__ void __launch_bounds__(256, 2) k_main(const float* __restrict__ img,
                                                 float* __restrict__ out) {
    extern __shared__ __align__(16) uint8_t smem[];
    uint8_t* bins = smem;              // 64KB
    uint8_t* hist = smem + 65536;      // 32KB

    const int tid  = threadIdx.x;
    const int lane = tid & 31;
    const int w    = tid >> 5;
    const int bc   = blockIdx.x;
    const float* __restrict__ ip = img + (size_t)bc * (HH * WW);

    // zero hists (32KB) while loads start
    {
        uint4* hz = (uint4*)hist;
        uint4 z; z.x = z.y = z.z = z.w = 0u;
        #pragma unroll
        for (int k = 0; k < 8; k++) hz[tid + 256 * k] = z;
    }

    // ---- Phase A: coalesced stream, quantize, pack 4 bins -> u32 ----
    const float4* __restrict__ ipv = (const float4*)ip;
    uint32_t* binw = (uint32_t*)bins;
    #pragma unroll 8
    for (int i = 0; i < 64; i++) {
        int idx = i * 256 + tid;
        float4 q = __ldcs(&ipv[idx]);
        // bit-identical to ref: fma(x,0.5,0.5) (exact mul => single rounding
        // equals (x*0.5)+0.5), then unfused *255, then floor.
        int b0 = __float2int_rd(__fmul_rn(__fmaf_rn(q.x, 0.5f, 0.5f), 255.0f)) - 127;
        int b1 = __float2int_rd(__fmul_rn(__fmaf_rn(q.y, 0.5f, 0.5f), 255.0f)) - 127;
        int b2 = __float2int_rd(__fmul_rn(__fmaf_rn(q.z, 0.5f, 0.5f), 255.0f)) - 127;
        int b3 = __float2int_rd(__fmul_rn(__fmaf_rn(q.w, 0.5f, 0.5f), 255.0f)) - 127;
        binw[idx] = (uint32_t)b0 | ((uint32_t)b1 << 8)
                  | ((uint32_t)b2 << 16) | ((uint32_t)b3 << 24);
    }
    __syncthreads();

    // ---- Phase B: warp w -> rings (w, 15-w), gather bins from smem ----
    uint8_t* h = hist + (w << 12);
    const int hb_lane = lane << 2;
    const int b = bc / 3, c = bc - b * 3;
    const int bin0 = bins[0];          // sentinel pixel's bin

    #pragma unroll
    for (int q = 0; q < 2; q++) {
        const int ring = q ? (15 - w) : w;
        const int n = g_cnt[ring];
        const int nsteps = (n + 63) >> 6;
        const int pad = (nsteps << 6) - n;   // sentinel entries (offset 0)
        const uint32_t* __restrict__ o32 =
            (const uint32_t*)(g_off + ring * RSTRIDE);

        #pragma unroll 4
        for (int s = 0; s < nsteps; s++) {
            uint32_t ow = o32[(s << 5) + lane];
            int v0 = bins[ow & 0xFFFFu];
            int v1 = bins[ow >> 16];
            h[((v0 << 5) & 0xF80) | hb_lane | (v0 & 3)] += 1;
            h[((v1 << 5) & 0xF80) | hb_lane | (v1 & 3)] += 1;
        }
        __syncwarp();

        // reduce: lane l owns bins 4l..4l+3; sum byte counters of 32 lanes.
        const uint32_t* hw = (const uint32_t*)h;
        uint32_t a02 = 0, a13 = 0;
        #pragma unroll
        for (int jj = 0; jj < 32; jj++) {
            int j = (jj + lane) & 31;
            uint32_t vv = hw[lane * 32 + j];
            a02 += vv & 0x00FF00FFu;
            a13 += (vv >> 8) & 0x00FF00FFu;
        }
        int h0 = (int)(a02 & 0xFFFFu), h2 = (int)(a02 >> 16);
        int h1 = (int)(a13 & 0xFFFFu), h3 = (int)(a13 >> 16);

        // subtract sentinel-pad counts from bin0
        if ((bin0 >> 2) == lane) {
            int qq = bin0 & 3;
            if (qq == 0) h0 -= pad;
            else if (qq == 1) h1 -= pad;
            else if (qq == 2) h2 -= pad;
            else h3 -= pad;
        }

        const int b0r = lane * 4;
        int sl  = h0 + h1 + h2 + h3;
        int sb  = h0 * b0r + h1 * (b0r + 1) + h2 * (b0r + 2) + h3 * (b0r + 3);
        int sb2 = h0 * b0r * b0r + h1 * (b0r + 1) * (b0r + 1)
                + h2 * (b0r + 2) * (b0r + 2) + h3 * (b0r + 3) * (b0r + 3);

        int sumb  = __reduce_add_sync(0xffffffffu, sb);
        int sumb2 = __reduce_add_sync(0xffffffffu, sb2);

        int sc = sl;
        #pragma unroll
        for (int d = 1; d < 32; d <<= 1) {
            int t2 = __shfl_up_sync(0xffffffffu, sc, d);
            if (lane >= d) sc += t2;
        }
        int cb = sc - sl;

        int k1 = (n - 1) >> 1, k2 = n >> 1;
        int c1 = 1 << 30, c2 = 1 << 30;
        {
            int t1 = k1 + 1;
            if (cb < t1 && t1 <= sc) {
                if      (cb + h0 >= t1)           c1 = b0r;
                else if (cb + h0 + h1 >= t1)      c1 = b0r + 1;
                else if (cb + h0 + h1 + h2 >= t1) c1 = b0r + 2;
                else                              c1 = b0r + 3;
            }
            int t2r = k2 + 1;
            if (cb < t2r && t2r <= sc) {
                if      (cb + h0 >= t2r)           c2 = b0r;
                else if (cb + h0 + h1 >= t2r)      c2 = b0r + 1;
                else if (cb + h0 + h1 + h2 >= t2r) c2 = b0r + 2;
                else                               c2 = b0r + 3;
            }
        }
        int m1 = __reduce_min_sync(0xffffffffu, c1);
        int m2 = __reduce_min_sync(0xffffffffu, c2);

        if (lane == 0) {
            double dn = (double)n;
            double mb = (double)sumb / dn;
            double mean = 127.0 + mb;
            double var = (double)sumb2 / dn - mb * mb;
            double sd = sqrt(var > 0.0 ? var : 0.0);
            double med = 127.0 + 0.5 * (double)(m1 + m2);
            int o = b * (NR * 9) + ring * 9 + c;
            out[o]     = (float)mean;
            out[o + 3] = (float)sd;
            out[o + 6] = (float)med;
        }
        __syncwarp();

        // rezero hist for the second ring
        if (q == 0) {
            uint4* hz = (uint4*)h;
            uint4 z; z.x = z.y = z.z = z.w = 0u;
            #pragma unroll
            for (int k = 0; k < 8; k++) hz[k * 32 + lane] = z;
            __syncwarp();
        }
    }
}

extern "C" void kernel_launch(void* const* d_in, const int* in_sizes, int n_in,
                              void* d_out, int out_size) {
    const float* img = (const float*)d_in[0];
    float* out = (float*)d_out;

    static int attr_set = 0;
    if (!attr_set) {
        cudaFuncSetAttribute(k_main, cudaFuncAttributeMaxDynamicSharedMemorySize,
                             98304);
        attr_set = 1;
    }

    k_zero<<<1, 32>>>();
    k_build<<<HH, WW>>>();
    k_main<<<768, 256, 98304>>>(img, out);
}